// round 5
// baseline (speedup 1.0000x reference)
#include <cuda_runtime.h>

// out[b, l, i, j] = emission[b, l, j] + transition[i, j]
// B=32, L=512, T=64. Output = 256 MB fp32, HBM-write-bound.
//
// Register-resident transition: block of 512 threads, thread t owns
// (i = t>>3, j8 = t&7) -> transition[i, j8*8..j8*8+7] loaded ONCE into regs.
// Loop over 8 (b,l) rows per block: per row each thread does one emission
// v8 load (8 distinct 32B segments per warp -> 2 L1 wavefronts, broadcast
// across the 4 i's) + one v8 .cs store (warp stores 1KB contiguous -> 8
// wavefronts). Load:store L1 wavefront ratio 0.25:1 (was 1:1).

__device__ __forceinline__ void ldg256(const float* p, float4& a, float4& b) {
    asm volatile("ld.global.nc.v8.f32 {%0,%1,%2,%3,%4,%5,%6,%7}, [%8];"
                 : "=f"(a.x), "=f"(a.y), "=f"(a.z), "=f"(a.w),
                   "=f"(b.x), "=f"(b.y), "=f"(b.z), "=f"(b.w)
                 : "l"(p));
}

__device__ __forceinline__ void stg256_cs(float* p, float4 a, float4 b) {
    asm volatile("st.global.cs.v8.f32 [%0], {%1,%2,%3,%4,%5,%6,%7,%8};"
                 :: "l"(p),
                    "f"(a.x), "f"(a.y), "f"(a.z), "f"(a.w),
                    "f"(b.x), "f"(b.y), "f"(b.z), "f"(b.w)
                 : "memory");
}

#define ROWS_PER_BLOCK 8

__global__ __launch_bounds__(512)
void CRF_53128745451552_kernel(const float* __restrict__ em,
                               const float* __restrict__ tr,
                               float* __restrict__ out) {
    int t  = threadIdx.x;
    int j8 = t & 7;     // j chunk (8 floats)
    int i  = t >> 3;    // 0..63 — warp covers 4 consecutive i, all j8

    // Transition chunk for this (i, j8): loaded once, register-resident.
    float4 t0, t1;
    ldg256(tr + (i << 6) + (j8 << 3), t0, t1);

    size_t bl0 = (size_t)blockIdx.x * ROWS_PER_BLOCK;
    const float* ep = em  + (bl0 << 6)  + (j8 << 3);
    float*       op = out + (bl0 << 12) + (i << 6) + (j8 << 3);

#pragma unroll
    for (int r = 0; r < ROWS_PER_BLOCK; r += 2) {
        float4 ea0, ea1, eb0, eb1;
        ldg256(ep + (size_t)r * 64,       ea0, ea1);   // emission[bl0+r,   j8*8..]
        ldg256(ep + (size_t)(r + 1) * 64, eb0, eb1);   // emission[bl0+r+1, j8*8..]

        float4 r0, r1;
        r0.x = ea0.x + t0.x;  r0.y = ea0.y + t0.y;
        r0.z = ea0.z + t0.z;  r0.w = ea0.w + t0.w;
        r1.x = ea1.x + t1.x;  r1.y = ea1.y + t1.y;
        r1.z = ea1.z + t1.z;  r1.w = ea1.w + t1.w;
        stg256_cs(op + (size_t)r * 4096, r0, r1);

        float4 s0, s1;
        s0.x = eb0.x + t0.x;  s0.y = eb0.y + t0.y;
        s0.z = eb0.z + t0.z;  s0.w = eb0.w + t0.w;
        s1.x = eb1.x + t1.x;  s1.y = eb1.y + t1.y;
        s1.z = eb1.z + t1.z;  s1.w = eb1.w + t1.w;
        stg256_cs(op + (size_t)(r + 1) * 4096, s0, s1);
    }
}

extern "C" void kernel_launch(void* const* d_in, const int* in_sizes, int n_in,
                              void* d_out, int out_size) {
    const float* em = (const float*)d_in[0];   // emission [32, 512, 64] fp32
    const float* tr = (const float*)d_in[1];   // transition [64, 64] fp32
    float* out = (float*)d_out;

    // 16384 rows / 8 rows-per-block = 2048 blocks of 512 threads.
    CRF_53128745451552_kernel<<<2048, 512>>>(em, tr, out);
}